// round 12
// baseline (speedup 1.0000x reference)
#include <cuda_runtime.h>
#include <cuda_fp16.h>

// B=4, S=1024, P=1024, E=1024, H=16, D=64, NS=2048
// out = [4,1024,1024] f32, present = [2,4,16,2048,64] f32 (packed after out)

__device__ __half g_qh[4096 * 1024];              // fp16, pre-scaled Q [token][1024]
__device__ __half g_ah[4096 * 1024];              // fp16 attn output
__device__ __half g_kh[4 * 16 * 2048 * 64];       // fp16 K, [b,h,key,d]
__device__ __half g_vh[4 * 16 * 2048 * 64];       // fp16 V, [b,h,key,d]
__device__ __half g_xh[4096 * 1024];              // fp16 x
__device__ __half g_wath[3072 * 1024];            // fp16 w_attn^T [N][K]
__device__ __half g_wprh[1024 * 1024];            // fp16 w_proj^T [N][K]

#define LOG2E 1.44269504088896f

__device__ __forceinline__ float ex2(float x) {
    float y;
    asm("ex2.approx.ftz.f32 %0, %1;" : "=f"(y) : "f"(x));
    return y;
}
__device__ __forceinline__ unsigned h2(float a, float b) {
    __half2 h = __floats2half2_rn(a, b);
    return *(unsigned*)&h;
}
__device__ __forceinline__ void mma_f16(float c[4], unsigned a0, unsigned a1,
                                        unsigned a2, unsigned a3,
                                        unsigned b0, unsigned b1) {
    asm volatile(
        "mma.sync.aligned.m16n8k16.row.col.f32.f16.f16.f32 "
        "{%0,%1,%2,%3}, {%4,%5,%6,%7}, {%8,%9}, {%0,%1,%2,%3};\n"
        : "+f"(c[0]), "+f"(c[1]), "+f"(c[2]), "+f"(c[3])
        : "r"(a0), "r"(a1), "r"(a2), "r"(a3), "r"(b0), "r"(b1));
}
__device__ __forceinline__ void ldsm4(unsigned& r0, unsigned& r1,
                                      unsigned& r2, unsigned& r3, unsigned addr) {
    asm volatile("ldmatrix.sync.aligned.m8n8.x4.shared.b16 {%0,%1,%2,%3}, [%4];"
                 : "=r"(r0), "=r"(r1), "=r"(r2), "=r"(r3) : "r"(addr));
}
__device__ __forceinline__ void ldsm4t(unsigned& r0, unsigned& r1,
                                       unsigned& r2, unsigned& r3, unsigned addr) {
    asm volatile("ldmatrix.sync.aligned.m8n8.x4.trans.shared.b16 {%0,%1,%2,%3}, [%4];"
                 : "=r"(r0), "=r"(r1), "=r"(r2), "=r"(r3) : "r"(addr));
}
__device__ __forceinline__ void cp16(unsigned dst_smem, const void* src) {
    asm volatile("cp.async.ca.shared.global [%0], [%1], 16;\n"
                 :: "r"(dst_smem), "l"(src));
}
__device__ __forceinline__ void cp_commit() {
    asm volatile("cp.async.commit_group;\n");
}
__device__ __forceinline__ void cp_wait0() {
    asm volatile("cp.async.wait_group 0;\n");
}
__device__ __forceinline__ void cp_wait1() {
    asm volatile("cp.async.wait_group 1;\n");
}

// ---------------------------------------------------------------------------
// fp32 -> fp16 rounding
// ---------------------------------------------------------------------------
__global__ __launch_bounds__(256) void round_half_kernel(
    const float* __restrict__ in, __half* __restrict__ out)
{
    int i = blockIdx.x * 256 + threadIdx.x;
    float4 v = *(const float4*)&in[(long)i * 4];
    uint2 r;
    r.x = h2(v.x, v.y);
    r.y = h2(v.z, v.w);
    *(uint2*)&out[(long)i * 4] = r;
}

// ---------------------------------------------------------------------------
// Round + transpose: in [K][N] fp32 -> out [N][K] fp16.
// ---------------------------------------------------------------------------
__global__ __launch_bounds__(256) void round_transpose_half_kernel(
    const float* __restrict__ in, __half* __restrict__ out, int K, int N)
{
    __shared__ float t[32][33];
    int n0 = blockIdx.x * 32;
    int k0 = blockIdx.y * 32;
    int tx = threadIdx.x & 31, ty = threadIdx.x >> 5;
#pragma unroll
    for (int j = 0; j < 4; ++j) {
        int k = k0 + ty + j * 8;
        t[ty + j * 8][tx] = in[(long)k * N + n0 + tx];
    }
    __syncthreads();
#pragma unroll
    for (int j = 0; j < 4; ++j) {
        int n = n0 + ty + j * 8;
        out[(long)n * K + k0 + tx] = __float2half_rn(t[tx][ty + j * 8]);
    }
}

// ---------------------------------------------------------------------------
// fp16 GEMM v7: 128x128 tile, 128 threads (4 warps 2x2, warp 64x64), BK=32.
// 6-slot cp.async ring, TWO k-tiles per barrier. Operands via ldmatrix.
// Smem rows: 32 halves (64B), swizzle chunk ^= (row>>1)&3. Dynamic smem 96KB.
// mode 0: C(fp32) = A@Bt^T + bias.
// mode 1: QKV split -> g_qh (scaled fp16) / present(fp32) + g_kh / + g_vh.
// ---------------------------------------------------------------------------
__global__ __launch_bounds__(128, 2) void gemm7_kernel(
    const __half* __restrict__ A, const __half* __restrict__ Bt,
    const float* __restrict__ bias, void* __restrict__ Cout,
    float* __restrict__ present, __half* __restrict__ kvh,
    __half* __restrict__ vh, int K, int mode)
{
    extern __shared__ __half dsmh[];   // 6 x 8192 halves (16KB/stage)

    const int tid = threadIdx.x;
    const int lane = tid & 31;
    const int wid = tid >> 5;
    const int wm = wid & 1;
    const int wn = wid >> 1;
    const int bm = blockIdx.y * 128;
    const int bn = blockIdx.x * 128;

    const unsigned sb = (unsigned)__cvta_generic_to_shared(dsmh);

    const int lrow = lane & 15;
    const int lhi = lane >> 4;

    // fragment ldsm byte offsets (relative to stage base)
    unsigned amat[4][2], bmat[4][2];
#pragma unroll
    for (int ks = 0; ks < 2; ++ks) {
#pragma unroll
        for (int mt = 0; mt < 4; ++mt) {
            int m = wm * 64 + mt * 16 + lrow;
            int ch = (2 * ks + lhi) ^ ((m >> 1) & 3);
            amat[mt][ks] = (unsigned)(m * 64 + 16 * ch);
        }
#pragma unroll
        for (int np = 0; np < 4; ++np) {
            int n = wn * 64 + np * 16 + lrow;
            int ch = (2 * ks + lhi) ^ ((n >> 1) & 3);
            bmat[np][ks] = (unsigned)(8192 + n * 64 + 16 * ch);
        }
    }

    auto stage = [&](int it) {
        const unsigned base = sb + (unsigned)((it % 6) * 16384);
#pragma unroll
        for (int j = 0; j < 4; ++j) {
            int id = j * 128 + tid;
            int row = id >> 2, c = id & 3;
            unsigned off = (unsigned)(row * 64 + 16 * (c ^ ((row >> 1) & 3)));
            cp16(base + off, A + (long)(bm + row) * K + it * 32 + c * 8);
            cp16(base + 8192 + off, Bt + (long)(bn + row) * K + it * 32 + c * 8);
        }
    };

    auto compute = [&](int it, float acc[4][8][4]) {
        const unsigned base = sb + (unsigned)((it % 6) * 16384);
#pragma unroll
        for (int ks = 0; ks < 2; ++ks) {
            unsigned af[4][4];
#pragma unroll
            for (int mt = 0; mt < 4; ++mt)
                ldsm4(af[mt][0], af[mt][1], af[mt][2], af[mt][3], base + amat[mt][ks]);
#pragma unroll
            for (int np = 0; np < 4; ++np) {
                unsigned b0, b1, b2, b3;
                ldsm4(b0, b1, b2, b3, base + bmat[np][ks]);
#pragma unroll
                for (int mt = 0; mt < 4; ++mt) {
                    mma_f16(acc[mt][2 * np + 0], af[mt][0], af[mt][1], af[mt][2], af[mt][3], b0, b2);
                    mma_f16(acc[mt][2 * np + 1], af[mt][0], af[mt][1], af[mt][2], af[mt][3], b1, b3);
                }
            }
        }
    };

    float acc[4][8][4] = {};

    const int nIter = K / 32;          // 32
    stage(0); stage(1); cp_commit();
    stage(2); stage(3); cp_commit();

    for (int i = 0; i < nIter / 2; ++i) {
        cp_wait1();
        __syncthreads();
        int t0 = 2 * i + 4, t1 = 2 * i + 5;
        if (t0 < nIter) stage(t0);
        if (t1 < nIter) stage(t1);
        cp_commit();
        compute(2 * i, acc);
        compute(2 * i + 1, acc);
    }

    // epilogue
    const int kvsel = (bn >= 2048) ? 1 : 0;
#pragma unroll
    for (int mt = 0; mt < 4; ++mt) {
        int row0 = bm + wm * 64 + mt * 16 + (lane >> 2);
#pragma unroll
        for (int nt = 0; nt < 8; ++nt) {
            int col = bn + wn * 64 + nt * 8 + 2 * (lane & 3);
            float2 bv = *(const float2*)&bias[col];
            float v00 = acc[mt][nt][0] + bv.x, v01 = acc[mt][nt][1] + bv.y;
            float v10 = acc[mt][nt][2] + bv.x, v11 = acc[mt][nt][3] + bv.y;
            if (mode == 0) {
                float* C = (float*)Cout;
                float2 r0 = {v00, v01}, r1 = {v10, v11};
                *(float2*)&C[(long)row0 * 1024 + col] = r0;
                *(float2*)&C[(long)(row0 + 8) * 1024 + col] = r1;
            } else if (bn < 1024) {
                __half* C = (__half*)Cout;
                const float sc = 0.125f * LOG2E;
                *(unsigned*)&C[(long)row0 * 1024 + col] = h2(v00 * sc, v01 * sc);
                *(unsigned*)&C[(long)(row0 + 8) * 1024 + col] = h2(v10 * sc, v11 * sc);
            } else {
                int colk = col - 1024 - (kvsel << 10);
                int h = colk >> 6, d = colk & 63;
                int bb = row0 >> 10, sN = row0 & 1023;
                long o0 = ((((long)(kvsel * 4 + bb) * 16 + h) * 2048) + 1024 + sN) * 64 + d;
                long o1 = o0 + 8 * 64;
                float2 p0 = {v00, v01}, p1 = {v10, v11};
                *(float2*)&present[o0] = p0;
                *(float2*)&present[o1] = p1;
                __half* dstbuf = (kvsel == 0) ? kvh : vh;
                long k0 = ((((long)bb * 16 + h) * 2048) + 1024 + sN) * 64 + d;
                *(unsigned*)&dstbuf[k0] = h2(v00, v01);
                *(unsigned*)&dstbuf[k0 + 8 * 64] = h2(v10, v11);
            }
        }
    }
}

// ---------------------------------------------------------------------------
// Copy PAST half: present (fp32) + g_kh / g_vh (fp16 [b,h,key,d]).
// ---------------------------------------------------------------------------
__global__ __launch_bounds__(256) void copy_past_kernel(
    const float* __restrict__ past, float* __restrict__ present,
    __half* __restrict__ kvh, __half* __restrict__ vh)
{
    int i4 = blockIdx.x * 256 + threadIdx.x;  // 0 .. 2097151
    int d4 = i4 & 15;
    int t = i4 >> 4;
    int p = t & 1023; t >>= 10;
    int h = t & 15;   t >>= 4;
    int b = t & 3;    t >>= 2;
    int kv = t;

    float4 v = *(const float4*)&past[(((long)(kv * 4 + b) * 16 + h) * 1024 + p) * 64 + d4 * 4];
    long dst = ((((long)(kv * 4 + b) * 16 + h) * 2048) + p) * 64 + d4 * 4;
    *(float4*)&present[dst] = v;
    long kd = ((((long)b * 16 + h) * 2048) + p) * 64 + d4 * 4;
    uint2 r;
    r.x = h2(v.x, v.y);
    r.y = h2(v.z, v.w);
    __half* dstbuf = (kv == 0) ? kvh : vh;
    *(uint2*)&dstbuf[kd] = r;
}

// ---------------------------------------------------------------------------
// Flash attention fp16: 3-stage ring (1 barrier/tile); K and V both [key][d],
// staged identically; PV B-fragments via ldmatrix.trans. Smem 48KB static.
// ---------------------------------------------------------------------------
__global__ __launch_bounds__(256, 2) void attn_kernel(
    const __half* __restrict__ gq,
    const __half* __restrict__ kvh,
    const __half* __restrict__ vhg,
    __half* __restrict__ aout)
{
    __shared__ __align__(16) __half smh[3 * 8192];

    const int tid = threadIdx.x;
    const int lane = tid & 31;
    const int w = tid >> 5;
    const int qt = 7 - (blockIdx.x & 7);          // long tiles first
    const int h  = (blockIdx.x >> 3) & 15;
    const int b  = blockIdx.x >> 7;

    const __half* kbase = kvh + (long)(b * 16 + h) * (2048 * 64);
    const __half* vbase = vhg + (long)(b * 16 + h) * (2048 * 64);

    const unsigned sb = (unsigned)__cvta_generic_to_shared(smh);

    // stage s: K tile (64x64 halves = 8KB) then V tile (8KB), same layout
    auto stage = [&](int kt) {
        const int s = kt % 3;
        const __half* kp = kbase + (long)kt * 64 * 64;
        const __half* vp = vbase + (long)kt * 64 * 64;
        unsigned kd = sb + (unsigned)(s * 16384);
        unsigned vd = kd + 8192;
#pragma unroll
        for (int l = 0; l < 2; ++l) {
            int idx = l * 256 + tid;
            int r = idx >> 3, c = idx & 7;
            unsigned doff = (unsigned)(r * 128 + 16 * (c ^ (r & 7)));
            cp16(kd + doff, kp + r * 64 + c * 8);
            cp16(vd + doff, vp + r * 64 + c * 8);
        }
    };

    // Q tile (128 x 64 halves = 16KB) staged at sb, then hoisted.
    {
        const __half* qb = gq + ((long)b * 1024 + qt * 128) * 1024 + h * 64;
#pragma unroll
        for (int l = 0; l < 4; ++l) {
            int idx = l * 256 + tid;
            int r = idx >> 3, c = idx & 7;
            unsigned doff = (unsigned)(r * 128 + 16 * (c ^ (r & 7)));
            cp16(sb + doff, qb + (long)r * 1024 + c * 8);
        }
    }
    cp_commit();
    cp_wait0();
    __syncthreads();

    const int lrow = lane & 15;
    const int lhi = lane >> 4;

    unsigned qf[4][4];
#pragma unroll
    for (int ks = 0; ks < 4; ++ks) {
        int m = 16 * w + lrow;
        int ch = (2 * ks + lhi) ^ (m & 7);
        ldsm4(qf[ks][0], qf[ks][1], qf[ks][2], qf[ks][3],
              sb + (unsigned)(m * 128 + 16 * ch));
    }
    __syncthreads();   // Q reads done; ring may overwrite

    const int diag0 = 16 + 2 * qt;
    const int nkt = diag0 + 2;

    stage(0); cp_commit();
    stage(1); cp_commit();

    float o[8][4] = {};
    float m0 = -1e30f, m1 = -1e30f, l0 = 0.f, l1 = 0.f;

    for (int kt = 0; kt < nkt; ++kt) {
        cp_wait1();
        __syncthreads();
        if (kt + 2 < nkt) stage(kt + 2);
        cp_commit();

        const unsigned kbuf = sb + (unsigned)((kt % 3) * 16384);
        const unsigned vbuf = kbuf + 8192;

        // S = Q K^T
        float s[8][4] = {};
#pragma unroll
        for (int ks = 0; ks < 4; ++ks) {
#pragma unroll
            for (int np = 0; np < 4; ++np) {
                int n = np * 16 + lrow;
                int ch = (2 * ks + lhi) ^ (n & 7);
                unsigned b0, b1, b2, b3;
                ldsm4(b0, b1, b2, b3, kbuf + (unsigned)(n * 128 + 16 * ch));
                mma_f16(s[2 * np + 0], qf[ks][0], qf[ks][1], qf[ks][2], qf[ks][3], b0, b2);
                mma_f16(s[2 * np + 1], qf[ks][0], qf[ks][1], qf[ks][2], qf[ks][3], b1, b3);
            }
        }

        if (kt >= diag0) {
            int q0 = 1024 + qt * 128 + 16 * w + (lane >> 2);
            int q1 = q0 + 8;
#pragma unroll
            for (int nt = 0; nt < 8; ++nt) {
                int kc = kt * 64 + nt * 8 + 2 * (lane & 3);
                if (kc > q0)     s[nt][0] = -14427.0f;
                if (kc + 1 > q0) s[nt][1] = -14427.0f;
                if (kc > q1)     s[nt][2] = -14427.0f;
                if (kc + 1 > q1) s[nt][3] = -14427.0f;
            }
        }

        // online softmax (exp2 domain)
        {
            float mt0 = -1e30f, mt1 = -1e30f;
#pragma unroll
            for (int nt = 0; nt < 8; ++nt) {
                mt0 = fmaxf(mt0, fmaxf(s[nt][0], s[nt][1]));
                mt1 = fmaxf(mt1, fmaxf(s[nt][2], s[nt][3]));
            }
            mt0 = fmaxf(mt0, __shfl_xor_sync(0xffffffffu, mt0, 1));
            mt0 = fmaxf(mt0, __shfl_xor_sync(0xffffffffu, mt0, 2));
            mt1 = fmaxf(mt1, __shfl_xor_sync(0xffffffffu, mt1, 1));
            mt1 = fmaxf(mt1, __shfl_xor_sync(0xffffffffu, mt1, 2));
            float mn0 = fmaxf(m0, mt0), mn1 = fmaxf(m1, mt1);
            float c0 = ex2(m0 - mn0), c1 = ex2(m1 - mn1);
            m0 = mn0; m1 = mn1;
            float rs0 = 0.f, rs1 = 0.f;
#pragma unroll
            for (int nt = 0; nt < 8; ++nt) {
                s[nt][0] = ex2(s[nt][0] - mn0);
                s[nt][1] = ex2(s[nt][1] - mn0);
                s[nt][2] = ex2(s[nt][2] - mn1);
                s[nt][3] = ex2(s[nt][3] - mn1);
                rs0 += s[nt][0] + s[nt][1];
                rs1 += s[nt][2] + s[nt][3];
            }
            rs0 += __shfl_xor_sync(0xffffffffu, rs0, 1);
            rs0 += __shfl_xor_sync(0xffffffffu, rs0, 2);
            rs1 += __shfl_xor_sync(0xffffffffu, rs1, 1);
            rs1 += __shfl_xor_sync(0xffffffffu, rs1, 2);
            l0 = l0 * c0 + rs0;
            l1 = l1 * c1 + rs1;
#pragma unroll
            for (int dt = 0; dt < 8; ++dt) {
                o[dt][0] *= c0; o[dt][1] *= c0;
                o[dt][2] *= c1; o[dt][3] *= c1;
            }
        }

        // O += P @ V : P A-frags = packed S C-frags; V B-frags via ldsm.trans
        // from [key][d] tile. kk = key chunk of 16: rows 16kk + (lane&15),
        // col chunk = 2*dtp + (lane>>4).
#pragma unroll
        for (int kk = 0; kk < 4; ++kk) {
            unsigned a0 = h2(s[2 * kk][0], s[2 * kk][1]);
            unsigned a1 = h2(s[2 * kk][2], s[2 * kk][3]);
            unsigned a2 = h2(s[2 * kk + 1][0], s[2 * kk + 1][1]);
            unsigned a3 = h2(s[2 * kk + 1][2], s[2 * kk + 1][3]);
            int krow = 16 * kk + lrow;
#pragma unroll
            for (int dtp = 0; dtp < 4; ++dtp) {
                int ch = (2 * dtp + lhi) ^ (krow & 7);
                unsigned b0, b1, b2, b3;
                ldsm4t(b0, b1, b2, b3, vbuf + (unsigned)(krow * 128 + 16 * ch));
                mma_f16(o[2 * dtp + 0], a0, a1, a2, a3, b0, b1);
                mma_f16(o[2 * dtp + 1], a0, a1, a2, a3, b2, b3);
            }
        }
    }

    // epilogue: normalize, fp16 output for proj GEMM
    {
        float inv0 = 1.0f / l0, inv1 = 1.0f / l1;
        int row0 = b * 1024 + qt * 128 + 16 * w + (lane >> 2);
        __half* ob = aout + (long)row0 * 1024 + h * 64;
#pragma unroll
        for (int dt = 0; dt < 8; ++dt) {
            int c = dt * 8 + 2 * (lane & 3);
            *(unsigned*)&ob[c] = h2(o[dt][0] * inv0, o[dt][1] * inv0);
            *(unsigned*)&ob[(long)8 * 1024 + c] = h2(o[dt][2] * inv1, o[dt][3] * inv1);
        }
    }
}

// ---------------------------------------------------------------------------
extern "C" void kernel_launch(void* const* d_in, const int* in_sizes, int n_in,
                              void* d_out, int out_size)
{
    const float* x      = (const float*)d_in[0];
    const float* past   = (const float*)d_in[1];
    const float* w_attn = (const float*)d_in[2];
    const float* b_attn = (const float*)d_in[3];
    const float* w_proj = (const float*)d_in[4];
    const float* b_proj = (const float*)d_in[5];

    float* out = (float*)d_out;
    float* present = out + 4194304;

    __half *qh_p, *ah_p, *kh_p, *vh_p, *xh_p, *wath_p, *wprh_p;
    cudaGetSymbolAddress((void**)&qh_p, g_qh);
    cudaGetSymbolAddress((void**)&ah_p, g_ah);
    cudaGetSymbolAddress((void**)&kh_p, g_kh);
    cudaGetSymbolAddress((void**)&vh_p, g_vh);
    cudaGetSymbolAddress((void**)&xh_p, g_xh);
    cudaGetSymbolAddress((void**)&wath_p, g_wath);
    cudaGetSymbolAddress((void**)&wprh_p, g_wprh);

    // 0) convert x to fp16; round+transpose weights to fp16 [N][K]
    round_half_kernel<<<4096, 256>>>(x, xh_p);
    {
        dim3 g(3072 / 32, 1024 / 32);
        round_transpose_half_kernel<<<g, 256>>>(w_attn, wath_p, 1024, 3072);
    }
    {
        dim3 g(1024 / 32, 1024 / 32);
        round_transpose_half_kernel<<<g, 256>>>(w_proj, wprh_p, 1024, 1024);
    }

    const int gemm_smem = 6 * 16384;   // 96KB dynamic
    cudaFuncSetAttribute(gemm7_kernel,
                         cudaFuncAttributeMaxDynamicSharedMemorySize, gemm_smem);

    // 1) QKV projection with fused Q-scale / present / K / V epilogue
    {
        dim3 grid(3072 / 128, 4096 / 128);
        gemm7_kernel<<<grid, 128, gemm_smem>>>(xh_p, wath_p, b_attn, qh_p,
                                               present, kh_p, vh_p, 1024, 1);
    }

    // 2) past half of present / K / V
    copy_past_kernel<<<2097152 / 256, 256>>>(past, present, kh_p, vh_p);

    // 3) attention
    attn_kernel<<<512, 256>>>(qh_p, kh_p, vh_p, ah_p);

    // 4) output projection
    {
        dim3 grid(1024 / 128, 4096 / 128);
        gemm7_kernel<<<grid, 128, gemm_smem>>>(ah_p, wprh_p, b_proj, out,
                                               nullptr, nullptr, nullptr, 1024, 0);
    }
}

// round 14
// speedup vs baseline: 1.0309x; 1.0309x over previous
#include <cuda_runtime.h>
#include <cuda_fp16.h>

// B=4, S=1024, P=1024, E=1024, H=16, D=64, NS=2048
// out = [4,1024,1024] f32, present = [2,4,16,2048,64] f32 (packed after out)

__device__ __half g_qh[4096 * 1024];              // fp16, pre-scaled Q [token][1024]
__device__ __half g_ah[4096 * 1024];              // fp16 attn output
__device__ __half g_kh[4 * 16 * 2048 * 64];       // fp16 K, [b,h,key,d]
__device__ __half g_vh[4 * 16 * 2048 * 64];       // fp16 V, [b,h,key,d]
__device__ __half g_xh[4096 * 1024];              // fp16 x
__device__ __half g_wath[3072 * 1024];            // fp16 w_attn^T [N][K]
__device__ __half g_wprh[1024 * 1024];            // fp16 w_proj^T [N][K]

#define LOG2E 1.44269504088896f

__device__ __forceinline__ float ex2(float x) {
    float y;
    asm("ex2.approx.ftz.f32 %0, %1;" : "=f"(y) : "f"(x));
    return y;
}
__device__ __forceinline__ unsigned h2(float a, float b) {
    __half2 h = __floats2half2_rn(a, b);
    return *(unsigned*)&h;
}
__device__ __forceinline__ void mma_f16(float c[4], unsigned a0, unsigned a1,
                                        unsigned a2, unsigned a3,
                                        unsigned b0, unsigned b1) {
    asm volatile(
        "mma.sync.aligned.m16n8k16.row.col.f32.f16.f16.f32 "
        "{%0,%1,%2,%3}, {%4,%5,%6,%7}, {%8,%9}, {%0,%1,%2,%3};\n"
        : "+f"(c[0]), "+f"(c[1]), "+f"(c[2]), "+f"(c[3])
        : "r"(a0), "r"(a1), "r"(a2), "r"(a3), "r"(b0), "r"(b1));
}
__device__ __forceinline__ void ldsm4(unsigned& r0, unsigned& r1,
                                      unsigned& r2, unsigned& r3, unsigned addr) {
    asm volatile("ldmatrix.sync.aligned.m8n8.x4.shared.b16 {%0,%1,%2,%3}, [%4];"
                 : "=r"(r0), "=r"(r1), "=r"(r2), "=r"(r3) : "r"(addr));
}
__device__ __forceinline__ void ldsm4t(unsigned& r0, unsigned& r1,
                                       unsigned& r2, unsigned& r3, unsigned addr) {
    asm volatile("ldmatrix.sync.aligned.m8n8.x4.trans.shared.b16 {%0,%1,%2,%3}, [%4];"
                 : "=r"(r0), "=r"(r1), "=r"(r2), "=r"(r3) : "r"(addr));
}
__device__ __forceinline__ void cp16(unsigned dst_smem, const void* src) {
    asm volatile("cp.async.ca.shared.global [%0], [%1], 16;\n"
                 :: "r"(dst_smem), "l"(src));
}
__device__ __forceinline__ void cp_commit() {
    asm volatile("cp.async.commit_group;\n");
}
__device__ __forceinline__ void cp_wait0() {
    asm volatile("cp.async.wait_group 0;\n");
}
__device__ __forceinline__ void cp_wait1() {
    asm volatile("cp.async.wait_group 1;\n");
}

// ---------------------------------------------------------------------------
// fp32 -> fp16 rounding
// ---------------------------------------------------------------------------
__global__ __launch_bounds__(256) void round_half_kernel(
    const float* __restrict__ in, __half* __restrict__ out)
{
    int i = blockIdx.x * 256 + threadIdx.x;
    float4 v = *(const float4*)&in[(long)i * 4];
    uint2 r;
    r.x = h2(v.x, v.y);
    r.y = h2(v.z, v.w);
    *(uint2*)&out[(long)i * 4] = r;
}

// ---------------------------------------------------------------------------
// Round + transpose: in [K][N] fp32 -> out [N][K] fp16.
// ---------------------------------------------------------------------------
__global__ __launch_bounds__(256) void round_transpose_half_kernel(
    const float* __restrict__ in, __half* __restrict__ out, int K, int N)
{
    __shared__ float t[32][33];
    int n0 = blockIdx.x * 32;
    int k0 = blockIdx.y * 32;
    int tx = threadIdx.x & 31, ty = threadIdx.x >> 5;
#pragma unroll
    for (int j = 0; j < 4; ++j) {
        int k = k0 + ty + j * 8;
        t[ty + j * 8][tx] = in[(long)k * N + n0 + tx];
    }
    __syncthreads();
#pragma unroll
    for (int j = 0; j < 4; ++j) {
        int n = n0 + ty + j * 8;
        out[(long)n * K + k0 + tx] = __float2half_rn(t[tx][ty + j * 8]);
    }
}

// ---------------------------------------------------------------------------
// fp16 GEMM (gemm6 structure + hoisted ldsm): 128x128 tile, 128 threads
// (4 warps 2x2, warp 64x64), BK=32, 3-stage cp.async ring, 1 barrier/iter.
// Smem rows: 32 halves (64B), swizzle chunk ^= (row>>1)&3.
// mode 0: C(fp32) = A@Bt^T + bias.
// mode 1: QKV split -> g_qh (scaled fp16) / present(fp32) + g_kh / + g_vh.
// ---------------------------------------------------------------------------
__global__ __launch_bounds__(128, 2) void gemm8_kernel(
    const __half* __restrict__ A, const __half* __restrict__ Bt,
    const float* __restrict__ bias, void* __restrict__ Cout,
    float* __restrict__ present, __half* __restrict__ kvh,
    __half* __restrict__ vh, int K, int mode)
{
    __shared__ __align__(16) __half smp[3 * 8192];  // 3 x (A 4096 + B 4096)

    const int tid = threadIdx.x;
    const int lane = tid & 31;
    const int wid = tid >> 5;
    const int wm = wid & 1;
    const int wn = wid >> 1;
    const int bm = blockIdx.y * 128;
    const int bn = blockIdx.x * 128;

    const unsigned sb = (unsigned)__cvta_generic_to_shared(smp);

    const int lrow = lane & 15;
    const int lhi = lane >> 4;

    unsigned amat[4][2], bmat[4][2];
#pragma unroll
    for (int ks = 0; ks < 2; ++ks) {
#pragma unroll
        for (int mt = 0; mt < 4; ++mt) {
            int m = wm * 64 + mt * 16 + lrow;
            int ch = (2 * ks + lhi) ^ ((m >> 1) & 3);
            amat[mt][ks] = (unsigned)(m * 64 + 16 * ch);
        }
#pragma unroll
        for (int np = 0; np < 4; ++np) {
            int n = wn * 64 + np * 16 + lrow;
            int ch = (2 * ks + lhi) ^ ((n >> 1) & 3);
            bmat[np][ks] = (unsigned)(8192 + n * 64 + 16 * ch);
        }
    }

    auto stage = [&](int it) {
        const unsigned base = sb + (unsigned)((it % 3) * 16384);
#pragma unroll
        for (int j = 0; j < 4; ++j) {
            int id = j * 128 + tid;
            int row = id >> 2, c = id & 3;
            unsigned off = (unsigned)(row * 64 + 16 * (c ^ ((row >> 1) & 3)));
            cp16(base + off, A + (long)(bm + row) * K + it * 32 + c * 8);
            cp16(base + 8192 + off, Bt + (long)(bn + row) * K + it * 32 + c * 8);
        }
    };

    float acc[4][8][4] = {};

    const int nIter = K / 32;
    stage(0); cp_commit();
    stage(1); cp_commit();

    for (int it = 0; it < nIter; ++it) {
        cp_wait1();
        __syncthreads();
        if (it + 2 < nIter) stage(it + 2);
        cp_commit();

        const unsigned base = sb + (unsigned)((it % 3) * 16384);
#pragma unroll
        for (int ks = 0; ks < 2; ++ks) {
            // hoist ALL fragment loads for this k-step (8 back-to-back ldsm)
            unsigned af[4][4], bf[4][4];
#pragma unroll
            for (int mt = 0; mt < 4; ++mt)
                ldsm4(af[mt][0], af[mt][1], af[mt][2], af[mt][3], base + amat[mt][ks]);
#pragma unroll
            for (int np = 0; np < 4; ++np)
                ldsm4(bf[np][0], bf[np][1], bf[np][2], bf[np][3], base + bmat[np][ks]);
#pragma unroll
            for (int np = 0; np < 4; ++np)
#pragma unroll
                for (int mt = 0; mt < 4; ++mt) {
                    mma_f16(acc[mt][2 * np + 0], af[mt][0], af[mt][1], af[mt][2], af[mt][3],
                            bf[np][0], bf[np][2]);
                    mma_f16(acc[mt][2 * np + 1], af[mt][0], af[mt][1], af[mt][2], af[mt][3],
                            bf[np][1], bf[np][3]);
                }
        }
    }

    // epilogue
    const int kvsel = (bn >= 2048) ? 1 : 0;
#pragma unroll
    for (int mt = 0; mt < 4; ++mt) {
        int row0 = bm + wm * 64 + mt * 16 + (lane >> 2);
#pragma unroll
        for (int nt = 0; nt < 8; ++nt) {
            int col = bn + wn * 64 + nt * 8 + 2 * (lane & 3);
            float2 bv = *(const float2*)&bias[col];
            float v00 = acc[mt][nt][0] + bv.x, v01 = acc[mt][nt][1] + bv.y;
            float v10 = acc[mt][nt][2] + bv.x, v11 = acc[mt][nt][3] + bv.y;
            if (mode == 0) {
                float* C = (float*)Cout;
                float2 r0 = {v00, v01}, r1 = {v10, v11};
                *(float2*)&C[(long)row0 * 1024 + col] = r0;
                *(float2*)&C[(long)(row0 + 8) * 1024 + col] = r1;
            } else if (bn < 1024) {
                __half* C = (__half*)Cout;
                const float sc = 0.125f * LOG2E;
                *(unsigned*)&C[(long)row0 * 1024 + col] = h2(v00 * sc, v01 * sc);
                *(unsigned*)&C[(long)(row0 + 8) * 1024 + col] = h2(v10 * sc, v11 * sc);
            } else {
                int colk = col - 1024 - (kvsel << 10);
                int h = colk >> 6, d = colk & 63;
                int bb = row0 >> 10, sN = row0 & 1023;
                long o0 = ((((long)(kvsel * 4 + bb) * 16 + h) * 2048) + 1024 + sN) * 64 + d;
                long o1 = o0 + 8 * 64;
                float2 p0 = {v00, v01}, p1 = {v10, v11};
                *(float2*)&present[o0] = p0;
                *(float2*)&present[o1] = p1;
                __half* dstbuf = (kvsel == 0) ? kvh : vh;
                long k0 = ((((long)bb * 16 + h) * 2048) + 1024 + sN) * 64 + d;
                *(unsigned*)&dstbuf[k0] = h2(v00, v01);
                *(unsigned*)&dstbuf[k0 + 8 * 64] = h2(v10, v11);
            }
        }
    }
}

// ---------------------------------------------------------------------------
// Copy PAST half: present (fp32) + g_kh / g_vh (fp16 [b,h,key,d]).
// ---------------------------------------------------------------------------
__global__ __launch_bounds__(256) void copy_past_kernel(
    const float* __restrict__ past, float* __restrict__ present,
    __half* __restrict__ kvh, __half* __restrict__ vh)
{
    int i4 = blockIdx.x * 256 + threadIdx.x;  // 0 .. 2097151
    int d4 = i4 & 15;
    int t = i4 >> 4;
    int p = t & 1023; t >>= 10;
    int h = t & 15;   t >>= 4;
    int b = t & 3;    t >>= 2;
    int kv = t;

    float4 v = *(const float4*)&past[(((long)(kv * 4 + b) * 16 + h) * 1024 + p) * 64 + d4 * 4];
    long dst = ((((long)(kv * 4 + b) * 16 + h) * 2048) + p) * 64 + d4 * 4;
    *(float4*)&present[dst] = v;
    long kd = ((((long)b * 16 + h) * 2048) + p) * 64 + d4 * 4;
    uint2 r;
    r.x = h2(v.x, v.y);
    r.y = h2(v.z, v.w);
    __half* dstbuf = (kv == 0) ? kvh : vh;
    *(uint2*)&dstbuf[kd] = r;
}

// ---------------------------------------------------------------------------
// Flash attention fp16: 3-stage ring, K and V both [key][d]; hoisted ldsm
// bursts before each mma chain; PV B-fragments via ldmatrix.trans.
// ---------------------------------------------------------------------------
__global__ __launch_bounds__(256, 2) void attn_kernel(
    const __half* __restrict__ gq,
    const __half* __restrict__ kvh,
    const __half* __restrict__ vhg,
    __half* __restrict__ aout)
{
    __shared__ __align__(16) __half smh[3 * 8192];

    const int tid = threadIdx.x;
    const int lane = tid & 31;
    const int w = tid >> 5;
    const int qt = 7 - (blockIdx.x & 7);          // long tiles first
    const int h  = (blockIdx.x >> 3) & 15;
    const int b  = blockIdx.x >> 7;

    const __half* kbase = kvh + (long)(b * 16 + h) * (2048 * 64);
    const __half* vbase = vhg + (long)(b * 16 + h) * (2048 * 64);

    const unsigned sb = (unsigned)__cvta_generic_to_shared(smh);

    auto stage = [&](int kt) {
        const int s = kt % 3;
        const __half* kp = kbase + (long)kt * 64 * 64;
        const __half* vp = vbase + (long)kt * 64 * 64;
        unsigned kd = sb + (unsigned)(s * 16384);
        unsigned vd = kd + 8192;
#pragma unroll
        for (int l = 0; l < 2; ++l) {
            int idx = l * 256 + tid;
            int r = idx >> 3, c = idx & 7;
            unsigned doff = (unsigned)(r * 128 + 16 * (c ^ (r & 7)));
            cp16(kd + doff, kp + r * 64 + c * 8);
            cp16(vd + doff, vp + r * 64 + c * 8);
        }
    };

    // Q tile staged at sb, then hoisted to registers.
    {
        const __half* qb = gq + ((long)b * 1024 + qt * 128) * 1024 + h * 64;
#pragma unroll
        for (int l = 0; l < 4; ++l) {
            int idx = l * 256 + tid;
            int r = idx >> 3, c = idx & 7;
            unsigned doff = (unsigned)(r * 128 + 16 * (c ^ (r & 7)));
            cp16(sb + doff, qb + (long)r * 1024 + c * 8);
        }
    }
    cp_commit();
    cp_wait0();
    __syncthreads();

    const int lrow = lane & 15;
    const int lhi = lane >> 4;

    unsigned qf[4][4];
#pragma unroll
    for (int ks = 0; ks < 4; ++ks) {
        int m = 16 * w + lrow;
        int ch = (2 * ks + lhi) ^ (m & 7);
        ldsm4(qf[ks][0], qf[ks][1], qf[ks][2], qf[ks][3],
              sb + (unsigned)(m * 128 + 16 * ch));
    }
    __syncthreads();   // Q reads done; ring may overwrite

    const int diag0 = 16 + 2 * qt;
    const int nkt = diag0 + 2;

    stage(0); cp_commit();
    stage(1); cp_commit();

    float o[8][4] = {};
    float m0 = -1e30f, m1 = -1e30f, l0 = 0.f, l1 = 0.f;

    for (int kt = 0; kt < nkt; ++kt) {
        cp_wait1();
        __syncthreads();
        if (kt + 2 < nkt) stage(kt + 2);
        cp_commit();

        const unsigned kbuf = sb + (unsigned)((kt % 3) * 16384);
        const unsigned vbuf = kbuf + 8192;

        // S = Q K^T : per ks, hoist 4 B-ldsm then 8 mma
        float s[8][4] = {};
#pragma unroll
        for (int ks = 0; ks < 4; ++ks) {
            unsigned bf[4][4];
#pragma unroll
            for (int np = 0; np < 4; ++np) {
                int n = np * 16 + lrow;
                int ch = (2 * ks + lhi) ^ (n & 7);
                ldsm4(bf[np][0], bf[np][1], bf[np][2], bf[np][3],
                      kbuf + (unsigned)(n * 128 + 16 * ch));
            }
#pragma unroll
            for (int np = 0; np < 4; ++np) {
                mma_f16(s[2 * np + 0], qf[ks][0], qf[ks][1], qf[ks][2], qf[ks][3],
                        bf[np][0], bf[np][2]);
                mma_f16(s[2 * np + 1], qf[ks][0], qf[ks][1], qf[ks][2], qf[ks][3],
                        bf[np][1], bf[np][3]);
            }
        }

        if (kt >= diag0) {
            int q0 = 1024 + qt * 128 + 16 * w + (lane >> 2);
            int q1 = q0 + 8;
#pragma unroll
            for (int nt = 0; nt < 8; ++nt) {
                int kc = kt * 64 + nt * 8 + 2 * (lane & 3);
                if (kc > q0)     s[nt][0] = -14427.0f;
                if (kc + 1 > q0) s[nt][1] = -14427.0f;
                if (kc > q1)     s[nt][2] = -14427.0f;
                if (kc + 1 > q1) s[nt][3] = -14427.0f;
            }
        }

        // online softmax (exp2 domain)
        {
            float mt0 = -1e30f, mt1 = -1e30f;
#pragma unroll
            for (int nt = 0; nt < 8; ++nt) {
                mt0 = fmaxf(mt0, fmaxf(s[nt][0], s[nt][1]));
                mt1 = fmaxf(mt1, fmaxf(s[nt][2], s[nt][3]));
            }
            mt0 = fmaxf(mt0, __shfl_xor_sync(0xffffffffu, mt0, 1));
            mt0 = fmaxf(mt0, __shfl_xor_sync(0xffffffffu, mt0, 2));
            mt1 = fmaxf(mt1, __shfl_xor_sync(0xffffffffu, mt1, 1));
            mt1 = fmaxf(mt1, __shfl_xor_sync(0xffffffffu, mt1, 2));
            float mn0 = fmaxf(m0, mt0), mn1 = fmaxf(m1, mt1);
            float c0 = ex2(m0 - mn0), c1 = ex2(m1 - mn1);
            m0 = mn0; m1 = mn1;
            float rs0 = 0.f, rs1 = 0.f;
#pragma unroll
            for (int nt = 0; nt < 8; ++nt) {
                s[nt][0] = ex2(s[nt][0] - mn0);
                s[nt][1] = ex2(s[nt][1] - mn0);
                s[nt][2] = ex2(s[nt][2] - mn1);
                s[nt][3] = ex2(s[nt][3] - mn1);
                rs0 += s[nt][0] + s[nt][1];
                rs1 += s[nt][2] + s[nt][3];
            }
            rs0 += __shfl_xor_sync(0xffffffffu, rs0, 1);
            rs0 += __shfl_xor_sync(0xffffffffu, rs0, 2);
            rs1 += __shfl_xor_sync(0xffffffffu, rs1, 1);
            rs1 += __shfl_xor_sync(0xffffffffu, rs1, 2);
            l0 = l0 * c0 + rs0;
            l1 = l1 * c1 + rs1;
#pragma unroll
            for (int dt = 0; dt < 8; ++dt) {
                o[dt][0] *= c0; o[dt][1] *= c0;
                o[dt][2] *= c1; o[dt][3] *= c1;
            }
        }

        // O += P @ V : per kk, hoist 4 ldsm.trans then 8 mma
#pragma unroll
        for (int kk = 0; kk < 4; ++kk) {
            unsigned a0 = h2(s[2 * kk][0], s[2 * kk][1]);
            unsigned a1 = h2(s[2 * kk][2], s[2 * kk][3]);
            unsigned a2 = h2(s[2 * kk + 1][0], s[2 * kk + 1][1]);
            unsigned a3 = h2(s[2 * kk + 1][2], s[2 * kk + 1][3]);
            int krow = 16 * kk + lrow;
            unsigned vf[4][4];
#pragma unroll
            for (int dtp = 0; dtp < 4; ++dtp) {
                int ch = (2 * dtp + lhi) ^ (krow & 7);
                ldsm4t(vf[dtp][0], vf[dtp][1], vf[dtp][2], vf[dtp][3],
                       vbuf + (unsigned)(krow * 128 + 16 * ch));
            }
#pragma unroll
            for (int dtp = 0; dtp < 4; ++dtp) {
                mma_f16(o[2 * dtp + 0], a0, a1, a2, a3, vf[dtp][0], vf[dtp][1]);
                mma_f16(o[2 * dtp + 1], a0, a1, a2, a3, vf[dtp][2], vf[dtp][3]);
            }
        }
    }

    // epilogue: normalize, fp16 output for proj GEMM
    {
        float inv0 = 1.0f / l0, inv1 = 1.0f / l1;
        int row0 = b * 1024 + qt * 128 + 16 * w + (lane >> 2);
        __half* ob = aout + (long)row0 * 1024 + h * 64;
#pragma unroll
        for (int dt = 0; dt < 8; ++dt) {
            int c = dt * 8 + 2 * (lane & 3);
            *(unsigned*)&ob[c] = h2(o[dt][0] * inv0, o[dt][1] * inv0);
            *(unsigned*)&ob[(long)8 * 1024 + c] = h2(o[dt][2] * inv1, o[dt][3] * inv1);
        }
    }
}

// ---------------------------------------------------------------------------
extern "C" void kernel_launch(void* const* d_in, const int* in_sizes, int n_in,
                              void* d_out, int out_size)
{
    const float* x      = (const float*)d_in[0];
    const float* past   = (const float*)d_in[1];
    const float* w_attn = (const float*)d_in[2];
    const float* b_attn = (const float*)d_in[3];
    const float* w_proj = (const float*)d_in[4];
    const float* b_proj = (const float*)d_in[5];

    float* out = (float*)d_out;
    float* present = out + 4194304;

    __half *qh_p, *ah_p, *kh_p, *vh_p, *xh_p, *wath_p, *wprh_p;
    cudaGetSymbolAddress((void**)&qh_p, g_qh);
    cudaGetSymbolAddress((void**)&ah_p, g_ah);
    cudaGetSymbolAddress((void**)&kh_p, g_kh);
    cudaGetSymbolAddress((void**)&vh_p, g_vh);
    cudaGetSymbolAddress((void**)&xh_p, g_xh);
    cudaGetSymbolAddress((void**)&wath_p, g_wath);
    cudaGetSymbolAddress((void**)&wprh_p, g_wprh);

    // 0) convert x to fp16; round+transpose weights to fp16 [N][K]
    round_half_kernel<<<4096, 256>>>(x, xh_p);
    {
        dim3 g(3072 / 32, 1024 / 32);
        round_transpose_half_kernel<<<g, 256>>>(w_attn, wath_p, 1024, 3072);
    }
    {
        dim3 g(1024 / 32, 1024 / 32);
        round_transpose_half_kernel<<<g, 256>>>(w_proj, wprh_p, 1024, 1024);
    }

    // 1) QKV projection with fused Q-scale / present / K / V epilogue
    {
        dim3 grid(3072 / 128, 4096 / 128);
        gemm8_kernel<<<grid, 128>>>(xh_p, wath_p, b_attn, qh_p,
                                    present, kh_p, vh_p, 1024, 1);
    }

    // 2) past half of present / K / V
    copy_past_kernel<<<2097152 / 256, 256>>>(past, present, kh_p, vh_p);

    // 3) attention
    attn_kernel<<<512, 256>>>(qh_p, kh_p, vh_p, ah_p);

    // 4) output projection
    {
        dim3 grid(1024 / 128, 4096 / 128);
        gemm8_kernel<<<grid, 128>>>(ah_p, wprh_p, b_proj, out,
                                    nullptr, nullptr, nullptr, 1024, 0);
    }
}

// round 15
// speedup vs baseline: 1.0445x; 1.0132x over previous
#include <cuda_runtime.h>
#include <cuda_fp16.h>

// B=4, S=1024, P=1024, E=1024, H=16, D=64, NS=2048
// out = [4,1024,1024] f32, present = [2,4,16,2048,64] f32 (packed after out)

__device__ __half g_qh[4096 * 1024];              // fp16, pre-scaled Q [token][1024]
__device__ __half g_ah[4096 * 1024];              // fp16 attn output
__device__ __half g_kh[4 * 16 * 2048 * 64];       // fp16 K, [b,h,key,d]
__device__ __half g_vh[4 * 16 * 2048 * 64];       // fp16 V, [b,h,key,d]
__device__ __half g_xh[4096 * 1024];              // fp16 x
__device__ __half g_wath[3072 * 1024];            // fp16 w_attn^T [N][K]
__device__ __half g_wprh[1024 * 1024];            // fp16 w_proj^T [N][K]

#define LOG2E 1.44269504088896f

__device__ __forceinline__ float ex2(float x) {
    float y;
    asm("ex2.approx.ftz.f32 %0, %1;" : "=f"(y) : "f"(x));
    return y;
}
__device__ __forceinline__ unsigned h2(float a, float b) {
    __half2 h = __floats2half2_rn(a, b);
    return *(unsigned*)&h;
}
__device__ __forceinline__ void mma_f16(float c[4], unsigned a0, unsigned a1,
                                        unsigned a2, unsigned a3,
                                        unsigned b0, unsigned b1) {
    asm volatile(
        "mma.sync.aligned.m16n8k16.row.col.f32.f16.f16.f32 "
        "{%0,%1,%2,%3}, {%4,%5,%6,%7}, {%8,%9}, {%0,%1,%2,%3};\n"
        : "+f"(c[0]), "+f"(c[1]), "+f"(c[2]), "+f"(c[3])
        : "r"(a0), "r"(a1), "r"(a2), "r"(a3), "r"(b0), "r"(b1));
}
__device__ __forceinline__ void ldsm4(unsigned& r0, unsigned& r1,
                                      unsigned& r2, unsigned& r3, unsigned addr) {
    asm volatile("ldmatrix.sync.aligned.m8n8.x4.shared.b16 {%0,%1,%2,%3}, [%4];"
                 : "=r"(r0), "=r"(r1), "=r"(r2), "=r"(r3) : "r"(addr));
}
__device__ __forceinline__ void ldsm4t(unsigned& r0, unsigned& r1,
                                       unsigned& r2, unsigned& r3, unsigned addr) {
    asm volatile("ldmatrix.sync.aligned.m8n8.x4.trans.shared.b16 {%0,%1,%2,%3}, [%4];"
                 : "=r"(r0), "=r"(r1), "=r"(r2), "=r"(r3) : "r"(addr));
}
__device__ __forceinline__ void cp16(unsigned dst_smem, const void* src) {
    asm volatile("cp.async.ca.shared.global [%0], [%1], 16;\n"
                 :: "r"(dst_smem), "l"(src));
}
__device__ __forceinline__ void cp_commit() {
    asm volatile("cp.async.commit_group;\n");
}
__device__ __forceinline__ void cp_wait0() {
    asm volatile("cp.async.wait_group 0;\n");
}
__device__ __forceinline__ void cp_wait1() {
    asm volatile("cp.async.wait_group 1;\n");
}

// ---------------------------------------------------------------------------
// fp32 -> fp16 rounding
// ---------------------------------------------------------------------------
__global__ __launch_bounds__(256) void round_half_kernel(
    const float* __restrict__ in, __half* __restrict__ out)
{
    int i = blockIdx.x * 256 + threadIdx.x;
    float4 v = *(const float4*)&in[(long)i * 4];
    uint2 r;
    r.x = h2(v.x, v.y);
    r.y = h2(v.z, v.w);
    *(uint2*)&out[(long)i * 4] = r;
}

// ---------------------------------------------------------------------------
// Round + transpose: in [K][N] fp32 -> out [N][K] fp16.
// ---------------------------------------------------------------------------
__global__ __launch_bounds__(256) void round_transpose_half_kernel(
    const float* __restrict__ in, __half* __restrict__ out, int K, int N)
{
    __shared__ float t[32][33];
    int n0 = blockIdx.x * 32;
    int k0 = blockIdx.y * 32;
    int tx = threadIdx.x & 31, ty = threadIdx.x >> 5;
#pragma unroll
    for (int j = 0; j < 4; ++j) {
        int k = k0 + ty + j * 8;
        t[ty + j * 8][tx] = in[(long)k * N + n0 + tx];
    }
    __syncthreads();
#pragma unroll
    for (int j = 0; j < 4; ++j) {
        int n = n0 + ty + j * 8;
        out[(long)n * K + k0 + tx] = __float2half_rn(t[tx][ty + j * 8]);
    }
}

// ---------------------------------------------------------------------------
// fp16 GEMM v9: 128x128 tile, 256 threads (8 warps as 2x4, warp 64x32), BK=32,
// 3-stage cp.async ring, 1 barrier/iter, hoisted ldsm. 16 warps/SM.
// Smem rows: 32 halves (64B), swizzle chunk ^= (row>>1)&3.
// mode 0: C(fp32) = A@Bt^T + bias.
// mode 1: QKV split -> g_qh (scaled fp16) / present(fp32) + g_kh / + g_vh.
// ---------------------------------------------------------------------------
__global__ __launch_bounds__(256, 2) void gemm9_kernel(
    const __half* __restrict__ A, const __half* __restrict__ Bt,
    const float* __restrict__ bias, void* __restrict__ Cout,
    float* __restrict__ present, __half* __restrict__ kvh,
    __half* __restrict__ vh, int K, int mode)
{
    __shared__ __align__(16) __half smp[3 * 8192];  // 3 x (A 4096 + B 4096)

    const int tid = threadIdx.x;
    const int lane = tid & 31;
    const int wid = tid >> 5;
    const int wm = wid & 1;           // 0..1 -> 64 rows
    const int wn = wid >> 1;          // 0..3 -> 32 cols
    const int bm = blockIdx.y * 128;
    const int bn = blockIdx.x * 128;

    const unsigned sb = (unsigned)__cvta_generic_to_shared(smp);

    const int lrow = lane & 15;
    const int lhi = lane >> 4;

    unsigned amat[4][2], bmat[2][2];
#pragma unroll
    for (int ks = 0; ks < 2; ++ks) {
#pragma unroll
        for (int mt = 0; mt < 4; ++mt) {
            int m = wm * 64 + mt * 16 + lrow;
            int ch = (2 * ks + lhi) ^ ((m >> 1) & 3);
            amat[mt][ks] = (unsigned)(m * 64 + 16 * ch);
        }
#pragma unroll
        for (int np = 0; np < 2; ++np) {
            int n = wn * 32 + np * 16 + lrow;
            int ch = (2 * ks + lhi) ^ ((n >> 1) & 3);
            bmat[np][ks] = (unsigned)(8192 + n * 64 + 16 * ch);
        }
    }

    // staging: 512 chunks per operand, 2 per thread each
    auto stage = [&](int it) {
        const unsigned base = sb + (unsigned)((it % 3) * 16384);
#pragma unroll
        for (int j = 0; j < 2; ++j) {
            int id = j * 256 + tid;
            int row = id >> 2, c = id & 3;
            unsigned off = (unsigned)(row * 64 + 16 * (c ^ ((row >> 1) & 3)));
            cp16(base + off, A + (long)(bm + row) * K + it * 32 + c * 8);
            cp16(base + 8192 + off, Bt + (long)(bn + row) * K + it * 32 + c * 8);
        }
    };

    float acc[4][4][4] = {};

    const int nIter = K / 32;
    stage(0); cp_commit();
    stage(1); cp_commit();

    for (int it = 0; it < nIter; ++it) {
        cp_wait1();
        __syncthreads();
        if (it + 2 < nIter) stage(it + 2);
        cp_commit();

        const unsigned base = sb + (unsigned)((it % 3) * 16384);
#pragma unroll
        for (int ks = 0; ks < 2; ++ks) {
            unsigned af[4][4], bf[2][4];
#pragma unroll
            for (int mt = 0; mt < 4; ++mt)
                ldsm4(af[mt][0], af[mt][1], af[mt][2], af[mt][3], base + amat[mt][ks]);
#pragma unroll
            for (int np = 0; np < 2; ++np)
                ldsm4(bf[np][0], bf[np][1], bf[np][2], bf[np][3], base + bmat[np][ks]);
#pragma unroll
            for (int np = 0; np < 2; ++np)
#pragma unroll
                for (int mt = 0; mt < 4; ++mt) {
                    mma_f16(acc[mt][2 * np + 0], af[mt][0], af[mt][1], af[mt][2], af[mt][3],
                            bf[np][0], bf[np][2]);
                    mma_f16(acc[mt][2 * np + 1], af[mt][0], af[mt][1], af[mt][2], af[mt][3],
                            bf[np][1], bf[np][3]);
                }
        }
    }

    // epilogue
    const int kvsel = (bn >= 2048) ? 1 : 0;
#pragma unroll
    for (int mt = 0; mt < 4; ++mt) {
        int row0 = bm + wm * 64 + mt * 16 + (lane >> 2);
#pragma unroll
        for (int nt = 0; nt < 4; ++nt) {
            int col = bn + wn * 32 + nt * 8 + 2 * (lane & 3);
            float2 bv = *(const float2*)&bias[col];
            float v00 = acc[mt][nt][0] + bv.x, v01 = acc[mt][nt][1] + bv.y;
            float v10 = acc[mt][nt][2] + bv.x, v11 = acc[mt][nt][3] + bv.y;
            if (mode == 0) {
                float* C = (float*)Cout;
                float2 r0 = {v00, v01}, r1 = {v10, v11};
                *(float2*)&C[(long)row0 * 1024 + col] = r0;
                *(float2*)&C[(long)(row0 + 8) * 1024 + col] = r1;
            } else if (bn < 1024) {
                __half* C = (__half*)Cout;
                const float sc = 0.125f * LOG2E;
                *(unsigned*)&C[(long)row0 * 1024 + col] = h2(v00 * sc, v01 * sc);
                *(unsigned*)&C[(long)(row0 + 8) * 1024 + col] = h2(v10 * sc, v11 * sc);
            } else {
                int colk = col - 1024 - (kvsel << 10);
                int h = colk >> 6, d = colk & 63;
                int bb = row0 >> 10, sN = row0 & 1023;
                long o0 = ((((long)(kvsel * 4 + bb) * 16 + h) * 2048) + 1024 + sN) * 64 + d;
                long o1 = o0 + 8 * 64;
                float2 p0 = {v00, v01}, p1 = {v10, v11};
                *(float2*)&present[o0] = p0;
                *(float2*)&present[o1] = p1;
                __half* dstbuf = (kvsel == 0) ? kvh : vh;
                long k0 = ((((long)bb * 16 + h) * 2048) + 1024 + sN) * 64 + d;
                *(unsigned*)&dstbuf[k0] = h2(v00, v01);
                *(unsigned*)&dstbuf[k0 + 8 * 64] = h2(v10, v11);
            }
        }
    }
}

// ---------------------------------------------------------------------------
// Copy PAST half: present (fp32) + g_kh / g_vh (fp16 [b,h,key,d]).
// ---------------------------------------------------------------------------
__global__ __launch_bounds__(256) void copy_past_kernel(
    const float* __restrict__ past, float* __restrict__ present,
    __half* __restrict__ kvh, __half* __restrict__ vh)
{
    int i4 = blockIdx.x * 256 + threadIdx.x;  // 0 .. 2097151
    int d4 = i4 & 15;
    int t = i4 >> 4;
    int p = t & 1023; t >>= 10;
    int h = t & 15;   t >>= 4;
    int b = t & 3;    t >>= 2;
    int kv = t;

    float4 v = *(const float4*)&past[(((long)(kv * 4 + b) * 16 + h) * 1024 + p) * 64 + d4 * 4];
    long dst = ((((long)(kv * 4 + b) * 16 + h) * 2048) + p) * 64 + d4 * 4;
    *(float4*)&present[dst] = v;
    long kd = ((((long)b * 16 + h) * 2048) + p) * 64 + d4 * 4;
    uint2 r;
    r.x = h2(v.x, v.y);
    r.y = h2(v.z, v.w);
    __half* dstbuf = (kv == 0) ? kvh : vh;
    *(uint2*)&dstbuf[kd] = r;
}

// ---------------------------------------------------------------------------
// Flash attention fp16 (unchanged from R14 best): 3-stage ring, hoisted ldsm,
// PV B-fragments via ldmatrix.trans.
// ---------------------------------------------------------------------------
__global__ __launch_bounds__(256, 2) void attn_kernel(
    const __half* __restrict__ gq,
    const __half* __restrict__ kvh,
    const __half* __restrict__ vhg,
    __half* __restrict__ aout)
{
    __shared__ __align__(16) __half smh[3 * 8192];

    const int tid = threadIdx.x;
    const int lane = tid & 31;
    const int w = tid >> 5;
    const int qt = 7 - (blockIdx.x & 7);          // long tiles first
    const int h  = (blockIdx.x >> 3) & 15;
    const int b  = blockIdx.x >> 7;

    const __half* kbase = kvh + (long)(b * 16 + h) * (2048 * 64);
    const __half* vbase = vhg + (long)(b * 16 + h) * (2048 * 64);

    const unsigned sb = (unsigned)__cvta_generic_to_shared(smh);

    auto stage = [&](int kt) {
        const int s = kt % 3;
        const __half* kp = kbase + (long)kt * 64 * 64;
        const __half* vp = vbase + (long)kt * 64 * 64;
        unsigned kd = sb + (unsigned)(s * 16384);
        unsigned vd = kd + 8192;
#pragma unroll
        for (int l = 0; l < 2; ++l) {
            int idx = l * 256 + tid;
            int r = idx >> 3, c = idx & 7;
            unsigned doff = (unsigned)(r * 128 + 16 * (c ^ (r & 7)));
            cp16(kd + doff, kp + r * 64 + c * 8);
            cp16(vd + doff, vp + r * 64 + c * 8);
        }
    };

    // Q tile staged at sb, then hoisted to registers.
    {
        const __half* qb = gq + ((long)b * 1024 + qt * 128) * 1024 + h * 64;
#pragma unroll
        for (int l = 0; l < 4; ++l) {
            int idx = l * 256 + tid;
            int r = idx >> 3, c = idx & 7;
            unsigned doff = (unsigned)(r * 128 + 16 * (c ^ (r & 7)));
            cp16(sb + doff, qb + (long)r * 1024 + c * 8);
        }
    }
    cp_commit();
    cp_wait0();
    __syncthreads();

    const int lrow = lane & 15;
    const int lhi = lane >> 4;

    unsigned qf[4][4];
#pragma unroll
    for (int ks = 0; ks < 4; ++ks) {
        int m = 16 * w + lrow;
        int ch = (2 * ks + lhi) ^ (m & 7);
        ldsm4(qf[ks][0], qf[ks][1], qf[ks][2], qf[ks][3],
              sb + (unsigned)(m * 128 + 16 * ch));
    }
    __syncthreads();   // Q reads done; ring may overwrite

    const int diag0 = 16 + 2 * qt;
    const int nkt = diag0 + 2;

    stage(0); cp_commit();
    stage(1); cp_commit();

    float o[8][4] = {};
    float m0 = -1e30f, m1 = -1e30f, l0 = 0.f, l1 = 0.f;

    for (int kt = 0; kt < nkt; ++kt) {
        cp_wait1();
        __syncthreads();
        if (kt + 2 < nkt) stage(kt + 2);
        cp_commit();

        const unsigned kbuf = sb + (unsigned)((kt % 3) * 16384);
        const unsigned vbuf = kbuf + 8192;

        // S = Q K^T : per ks, hoist 4 B-ldsm then 8 mma
        float s[8][4] = {};
#pragma unroll
        for (int ks = 0; ks < 4; ++ks) {
            unsigned bf[4][4];
#pragma unroll
            for (int np = 0; np < 4; ++np) {
                int n = np * 16 + lrow;
                int ch = (2 * ks + lhi) ^ (n & 7);
                ldsm4(bf[np][0], bf[np][1], bf[np][2], bf[np][3],
                      kbuf + (unsigned)(n * 128 + 16 * ch));
            }
#pragma unroll
            for (int np = 0; np < 4; ++np) {
                mma_f16(s[2 * np + 0], qf[ks][0], qf[ks][1], qf[ks][2], qf[ks][3],
                        bf[np][0], bf[np][2]);
                mma_f16(s[2 * np + 1], qf[ks][0], qf[ks][1], qf[ks][2], qf[ks][3],
                        bf[np][1], bf[np][3]);
            }
        }

        if (kt >= diag0) {
            int q0 = 1024 + qt * 128 + 16 * w + (lane >> 2);
            int q1 = q0 + 8;
#pragma unroll
            for (int nt = 0; nt < 8; ++nt) {
                int kc = kt * 64 + nt * 8 + 2 * (lane & 3);
                if (kc > q0)     s[nt][0] = -14427.0f;
                if (kc + 1 > q0) s[nt][1] = -14427.0f;
                if (kc > q1)     s[nt][2] = -14427.0f;
                if (kc + 1 > q1) s[nt][3] = -14427.0f;
            }
        }

        // online softmax (exp2 domain)
        {
            float mt0 = -1e30f, mt1 = -1e30f;
#pragma unroll
            for (int nt = 0; nt < 8; ++nt) {
                mt0 = fmaxf(mt0, fmaxf(s[nt][0], s[nt][1]));
                mt1 = fmaxf(mt1, fmaxf(s[nt][2], s[nt][3]));
            }
            mt0 = fmaxf(mt0, __shfl_xor_sync(0xffffffffu, mt0, 1));
            mt0 = fmaxf(mt0, __shfl_xor_sync(0xffffffffu, mt0, 2));
            mt1 = fmaxf(mt1, __shfl_xor_sync(0xffffffffu, mt1, 1));
            mt1 = fmaxf(mt1, __shfl_xor_sync(0xffffffffu, mt1, 2));
            float mn0 = fmaxf(m0, mt0), mn1 = fmaxf(m1, mt1);
            float c0 = ex2(m0 - mn0), c1 = ex2(m1 - mn1);
            m0 = mn0; m1 = mn1;
            float rs0 = 0.f, rs1 = 0.f;
#pragma unroll
            for (int nt = 0; nt < 8; ++nt) {
                s[nt][0] = ex2(s[nt][0] - mn0);
                s[nt][1] = ex2(s[nt][1] - mn0);
                s[nt][2] = ex2(s[nt][2] - mn1);
                s[nt][3] = ex2(s[nt][3] - mn1);
                rs0 += s[nt][0] + s[nt][1];
                rs1 += s[nt][2] + s[nt][3];
            }
            rs0 += __shfl_xor_sync(0xffffffffu, rs0, 1);
            rs0 += __shfl_xor_sync(0xffffffffu, rs0, 2);
            rs1 += __shfl_xor_sync(0xffffffffu, rs1, 1);
            rs1 += __shfl_xor_sync(0xffffffffu, rs1, 2);
            l0 = l0 * c0 + rs0;
            l1 = l1 * c1 + rs1;
#pragma unroll
            for (int dt = 0; dt < 8; ++dt) {
                o[dt][0] *= c0; o[dt][1] *= c0;
                o[dt][2] *= c1; o[dt][3] *= c1;
            }
        }

        // O += P @ V : per kk, hoist 4 ldsm.trans then 8 mma
#pragma unroll
        for (int kk = 0; kk < 4; ++kk) {
            unsigned a0 = h2(s[2 * kk][0], s[2 * kk][1]);
            unsigned a1 = h2(s[2 * kk][2], s[2 * kk][3]);
            unsigned a2 = h2(s[2 * kk + 1][0], s[2 * kk + 1][1]);
            unsigned a3 = h2(s[2 * kk + 1][2], s[2 * kk + 1][3]);
            int krow = 16 * kk + lrow;
            unsigned vf[4][4];
#pragma unroll
            for (int dtp = 0; dtp < 4; ++dtp) {
                int ch = (2 * dtp + lhi) ^ (krow & 7);
                ldsm4t(vf[dtp][0], vf[dtp][1], vf[dtp][2], vf[dtp][3],
                       vbuf + (unsigned)(krow * 128 + 16 * ch));
            }
#pragma unroll
            for (int dtp = 0; dtp < 4; ++dtp) {
                mma_f16(o[2 * dtp + 0], a0, a1, a2, a3, vf[dtp][0], vf[dtp][1]);
                mma_f16(o[2 * dtp + 1], a0, a1, a2, a3, vf[dtp][2], vf[dtp][3]);
            }
        }
    }

    // epilogue: normalize, fp16 output for proj GEMM
    {
        float inv0 = 1.0f / l0, inv1 = 1.0f / l1;
        int row0 = b * 1024 + qt * 128 + 16 * w + (lane >> 2);
        __half* ob = aout + (long)row0 * 1024 + h * 64;
#pragma unroll
        for (int dt = 0; dt < 8; ++dt) {
            int c = dt * 8 + 2 * (lane & 3);
            *(unsigned*)&ob[c] = h2(o[dt][0] * inv0, o[dt][1] * inv0);
            *(unsigned*)&ob[(long)8 * 1024 + c] = h2(o[dt][2] * inv1, o[dt][3] * inv1);
        }
    }
}

// ---------------------------------------------------------------------------
extern "C" void kernel_launch(void* const* d_in, const int* in_sizes, int n_in,
                              void* d_out, int out_size)
{
    const float* x      = (const float*)d_in[0];
    const float* past   = (const float*)d_in[1];
    const float* w_attn = (const float*)d_in[2];
    const float* b_attn = (const float*)d_in[3];
    const float* w_proj = (const float*)d_in[4];
    const float* b_proj = (const float*)d_in[5];

    float* out = (float*)d_out;
    float* present = out + 4194304;

    __half *qh_p, *ah_p, *kh_p, *vh_p, *xh_p, *wath_p, *wprh_p;
    cudaGetSymbolAddress((void**)&qh_p, g_qh);
    cudaGetSymbolAddress((void**)&ah_p, g_ah);
    cudaGetSymbolAddress((void**)&kh_p, g_kh);
    cudaGetSymbolAddress((void**)&vh_p, g_vh);
    cudaGetSymbolAddress((void**)&xh_p, g_xh);
    cudaGetSymbolAddress((void**)&wath_p, g_wath);
    cudaGetSymbolAddress((void**)&wprh_p, g_wprh);

    // 0) convert x to fp16; round+transpose weights to fp16 [N][K]
    round_half_kernel<<<4096, 256>>>(x, xh_p);
    {
        dim3 g(3072 / 32, 1024 / 32);
        round_transpose_half_kernel<<<g, 256>>>(w_attn, wath_p, 1024, 3072);
    }
    {
        dim3 g(1024 / 32, 1024 / 32);
        round_transpose_half_kernel<<<g, 256>>>(w_proj, wprh_p, 1024, 1024);
    }

    // 1) QKV projection with fused Q-scale / present / K / V epilogue
    {
        dim3 grid(3072 / 128, 4096 / 128);
        gemm9_kernel<<<grid, 256>>>(xh_p, wath_p, b_attn, qh_p,
                                    present, kh_p, vh_p, 1024, 1);
    }

    // 2) past half of present / K / V
    copy_past_kernel<<<2097152 / 256, 256>>>(past, present, kh_p, vh_p);

    // 3) attention
    attn_kernel<<<512, 256>>>(qh_p, kh_p, vh_p, ah_p);

    // 4) output projection
    {
        dim3 grid(1024 / 128, 4096 / 128);
        gemm9_kernel<<<grid, 256>>>(ah_p, wprh_p, b_proj, out,
                                    nullptr, nullptr, nullptr, 1024, 0);
    }
}